// round 11
// baseline (speedup 1.0000x reference)
#include <cuda_runtime.h>
#include <cuda_bf16.h>
#include <stdint.h>

// out[src[e]*16 + k] += attr_flat[k*E + e]
// Round-10: single fused kernel. First ZBLOCKS blocks zero the output slice
// (hidden behind the load/transpose phase), everyone spins on a done-counter
// before the RED scatter. Counters self-reset for graph replay.

#define TILE 256
#define ZBLOCKS 296   // 2 per SM: guaranteed wave-1 residents -> no deadlock

__device__ int g_zero_done = 0;
__device__ int g_finished  = 0;

__global__ __launch_bounds__(TILE) void fused_scatter_f16_kernel(
        const float* __restrict__ attr,
        const int* __restrict__ src_idx,
        float* __restrict__ out,
        int E, int n4, int ntail, int zb) {
    __shared__ float vals[TILE][20];   // edge-major, 80B rows (16B-aligned)
    __shared__ int   sidx[TILE];

    const int t = threadIdx.x;
    const int bid = blockIdx.x;
    const int base = bid * TILE;
    const int e = base + t;

    // ---- Phase A (zeroing blocks only): clear output, signal ----
    if (bid < zb) {
        float4 z = make_float4(0.f, 0.f, 0.f, 0.f);
        float4* o4 = (float4*)out;
        for (int i = bid * TILE + t; i < n4; i += zb * TILE)
            o4[i] = z;                          // coalesced STG.128
        if (bid == 0 && t < ntail) out[n4 * 4 + t] = 0.f;
        __threadfence();                        // release zeros to L2
        __syncthreads();                        // all threads fenced
        if (t == 0) atomicAdd(&g_zero_done, 1);
    }

    // ---- Phase B: load tile (coalesced feature-major) + transpose ----
    if (e < E) {
        sidx[t] = src_idx[e];
        float v[16];
#pragma unroll
        for (int k = 0; k < 16; k++)
            v[k] = attr[(size_t)k * E + e];
#pragma unroll
        for (int kg = 0; kg < 4; kg++) {
            float4 p = make_float4(v[4*kg+0], v[4*kg+1], v[4*kg+2], v[4*kg+3]);
            *reinterpret_cast<float4*>(&vals[t][4*kg]) = p;
        }
    }
    __syncthreads();

    // ---- Phase C: wait until output is zeroed ----
    if (t == 0) {
        while (*(volatile int*)&g_zero_done < zb)
            __nanosleep(64);
    }
    __syncthreads();

    // ---- Phase D: scatter. lane l -> edge (l/4), feature-group (l%4):
    // 4 consecutive lanes cover one contiguous 64B output row.
    const int kg = t & 3;
    const int eg = t >> 2;           // 0..63
#pragma unroll
    for (int q = 0; q < 4; q++) {
        const int el = eg + 64 * q;  // 0..255
        if (base + el < E) {
            const int s = sidx[el];                          // 4-lane broadcast
            float4 p = *reinterpret_cast<const float4*>(&vals[el][4*kg]);
            float* dst = out + (size_t)s * 16 + 4 * kg;      // 16B-aligned
            asm volatile("red.global.add.v4.f32 [%0], {%1, %2, %3, %4};"
                         :: "l"(dst), "f"(p.x), "f"(p.y), "f"(p.z), "f"(p.w)
                         : "memory");
        }
    }

    // ---- Phase E: last block resets counters (safe: all passed the wait) ----
    if (t == 0) {
        int f = atomicAdd(&g_finished, 1);
        if (f == (int)gridDim.x - 1) {
            g_finished  = 0;
            g_zero_done = 0;
        }
    }
}

// Generic fallback for F != 16 (two-kernel path).
__global__ void zero_out_kernel(float4* __restrict__ out, int n4) {
    for (int i = blockIdx.x * blockDim.x + threadIdx.x; i < n4;
         i += gridDim.x * blockDim.x)
        out[i] = make_float4(0.f, 0.f, 0.f, 0.f);
}
__global__ void scatter_generic_kernel(const float* __restrict__ attr,
                                       const int* __restrict__ src_idx,
                                       float* __restrict__ out,
                                       int E, int F) {
    int e = blockIdx.x * blockDim.x + threadIdx.x;
    if (e >= E) return;
    const int s = src_idx[e];
    for (int k = 0; k < F; k++)
        atomicAdd(&out[(size_t)s * F + k], attr[(size_t)k * E + e]);
}

extern "C" void kernel_launch(void* const* d_in, const int* in_sizes, int n_in,
                              void* d_out, int out_size) {
    const float* attr = (const float*)d_in[0];   // (E, F) float32, flat
    const int*   idx  = (const int*)d_in[1];     // (2, E) int32; row 0 = src

    const int E = in_sizes[1] / 2;
    const int F = in_sizes[0] / E;
    float* out = (float*)d_out;

    if (F == 16) {
        int blocks = (E + TILE - 1) / TILE;
        int n4 = out_size / 4;
        int ntail = out_size & 3;
        int zb = blocks < ZBLOCKS ? blocks : ZBLOCKS;
        fused_scatter_f16_kernel<<<blocks, TILE>>>(attr, idx, out,
                                                   E, n4, ntail, zb);
    } else {
        int n4 = out_size / 4;
        int zblocks = (n4 + 1023) / 1024;
        if (zblocks > 296) zblocks = 296;
        zero_out_kernel<<<zblocks, 1024>>>((float4*)out, n4);
        int blocks = (E + 255) / 256;
        scatter_generic_kernel<<<blocks, 256>>>(attr, idx, out, E, F);
    }
}

// round 12
// speedup vs baseline: 1.0828x; 1.0828x over previous
#include <cuda_runtime.h>
#include <cuda_bf16.h>
#include <stdint.h>

// out[src[e]*16 + k] += attr_flat[k*E + e]
// Round-11: round-9's proven scatter (62.1us) + PDL overlap: the scatter grid
// launches while zero_out drains, runs its LDG+transpose preamble, and
// cudaGridDependencySynchronize()s only right before the REDs.

#define TILE 256

__global__ __launch_bounds__(1024) void zero_out_kernel(float4* __restrict__ out,
                                                        int n4) {
    for (int i = blockIdx.x * blockDim.x + threadIdx.x; i < n4;
         i += gridDim.x * blockDim.x)
        out[i] = make_float4(0.f, 0.f, 0.f, 0.f);
    // Allow the dependent scatter grid to begin launching now; its
    // cudaGridDependencySynchronize() still waits for our stores to flush.
    cudaTriggerProgrammaticLaunchCompletion();
}

__global__ __launch_bounds__(TILE) void scatter_f16_kernel(
        const float* __restrict__ attr,
        const int* __restrict__ src_idx,
        float* __restrict__ out,
        int E) {
    // Edge-major staging: row stride 20 floats (80B, 16B-aligned).
    __shared__ float vals[TILE][20];
    __shared__ int   sidx[TILE];

    const int t = threadIdx.x;
    const int base = blockIdx.x * TILE;
    const int e = base + t;

    // ---- Preamble (independent of out): coalesced loads + transpose ----
    if (e < E) {
        sidx[t] = src_idx[e];
        float v[16];
#pragma unroll
        for (int k = 0; k < 16; k++)
            v[k] = attr[(size_t)k * E + e];
#pragma unroll
        for (int kg = 0; kg < 4; kg++) {
            float4 p = make_float4(v[4*kg+0], v[4*kg+1], v[4*kg+2], v[4*kg+3]);
            *reinterpret_cast<float4*>(&vals[t][4*kg]) = p;
        }
    }
    __syncthreads();

    // ---- Wait for zero_out_kernel's writes to be visible ----
    cudaGridDependencySynchronize();

    // ---- Scatter: lane l -> edge (l/4), feature-group (l%4) ----
    // 4 consecutive lanes cover one contiguous 64B output row -> the warp's
    // RED.v4 merges into ~8 wavefronts instead of 32.
    const int kg = t & 3;
    const int eg = t >> 2;           // 0..63
#pragma unroll
    for (int q = 0; q < 4; q++) {
        const int el = eg + 64 * q;  // 0..255
        if (base + el < E) {
            const int s = sidx[el];                          // 4-lane broadcast
            float4 p = *reinterpret_cast<const float4*>(&vals[el][4*kg]);
            float* dst = out + (size_t)s * 16 + 4 * kg;      // 16B-aligned
            asm volatile("red.global.add.v4.f32 [%0], {%1, %2, %3, %4};"
                         :: "l"(dst), "f"(p.x), "f"(p.y), "f"(p.z), "f"(p.w)
                         : "memory");
        }
    }
}

// Generic fallback for F != 16 (plain serialized two-kernel path).
__global__ void zero_out_plain(float4* __restrict__ out, int n4) {
    for (int i = blockIdx.x * blockDim.x + threadIdx.x; i < n4;
         i += gridDim.x * blockDim.x)
        out[i] = make_float4(0.f, 0.f, 0.f, 0.f);
}
__global__ void scatter_generic_kernel(const float* __restrict__ attr,
                                       const int* __restrict__ src_idx,
                                       float* __restrict__ out,
                                       int E, int F) {
    int e = blockIdx.x * blockDim.x + threadIdx.x;
    if (e >= E) return;
    const int s = src_idx[e];
    for (int k = 0; k < F; k++)
        atomicAdd(&out[(size_t)s * F + k], attr[(size_t)k * E + e]);
}

extern "C" void kernel_launch(void* const* d_in, const int* in_sizes, int n_in,
                              void* d_out, int out_size) {
    const float* attr = (const float*)d_in[0];   // (E, F) float32, flat
    const int*   idx  = (const int*)d_in[1];     // (2, E) int32; row 0 = src

    const int E = in_sizes[1] / 2;
    const int F = in_sizes[0] / E;
    float* out = (float*)d_out;

    if (F == 16) {
        int n4 = out_size / 4;
        int zblocks = (n4 + 1023) / 1024;
        if (zblocks > 296) zblocks = 296;        // grid-stride, <=2 waves
        zero_out_kernel<<<zblocks, 1024>>>((float4*)out, n4);

        int blocks = (E + TILE - 1) / TILE;
        cudaLaunchConfig_t cfg = {};
        cfg.gridDim = dim3((unsigned)blocks, 1, 1);
        cfg.blockDim = dim3(TILE, 1, 1);
        cfg.dynamicSmemBytes = 0;
        cfg.stream = 0;                          // same (captured) stream
        cudaLaunchAttribute attrs[1];
        attrs[0].id = cudaLaunchAttributeProgrammaticStreamSerialization;
        attrs[0].val.programmaticStreamSerializationAllowed = 1;
        cfg.attrs = attrs;
        cfg.numAttrs = 1;
        cudaLaunchKernelEx(&cfg, scatter_f16_kernel, attr, idx, out, E);
    } else {
        int n4 = out_size / 4;
        int zblocks = (n4 + 1023) / 1024;
        if (zblocks > 296) zblocks = 296;
        zero_out_plain<<<zblocks, 1024>>>((float4*)out, n4);
        int blocks = (E + 255) / 256;
        scatter_generic_kernel<<<blocks, 256>>>(attr, idx, out, E, F);
    }
}

// round 13
// speedup vs baseline: 1.1061x; 1.0215x over previous
#include <cuda_runtime.h>
#include <cuda_bf16.h>
#include <stdint.h>

// out[src[e]*16 + k] += attr_flat[k*E + e]
// Round-12: same proven scatter (62.6us) + PDL with the launch trigger at
// zero_out ENTRY: the scatter grid launches immediately and overlaps its
// LDG/transpose preamble with the zeroing; cudaGridDependencySynchronize()
// (which always waits for full primary completion) guards the REDs.

#define TILE 256

__global__ __launch_bounds__(1024) void zero_out_kernel(float4* __restrict__ out,
                                                        int n4) {
    // Fire first: dependent grid may start launching now. Correctness is
    // carried by the consumer's cudaGridDependencySynchronize(), which waits
    // for this grid's completion + memory flush regardless of trigger timing.
    cudaTriggerProgrammaticLaunchCompletion();
    for (int i = blockIdx.x * blockDim.x + threadIdx.x; i < n4;
         i += gridDim.x * blockDim.x)
        out[i] = make_float4(0.f, 0.f, 0.f, 0.f);
}

__global__ __launch_bounds__(TILE) void scatter_f16_kernel(
        const float* __restrict__ attr,
        const int* __restrict__ src_idx,
        float* __restrict__ out,
        int E) {
    // Edge-major staging: row stride 20 floats (80B, 16B-aligned).
    __shared__ float vals[TILE][20];
    __shared__ int   sidx[TILE];

    const int t = threadIdx.x;
    const int base = blockIdx.x * TILE;
    const int e = base + t;

    // ---- Preamble (independent of out): coalesced loads + transpose ----
    if (e < E) {
        sidx[t] = src_idx[e];
        float v[16];
#pragma unroll
        for (int k = 0; k < 16; k++)
            v[k] = attr[(size_t)k * E + e];
#pragma unroll
        for (int kg = 0; kg < 4; kg++) {
            float4 p = make_float4(v[4*kg+0], v[4*kg+1], v[4*kg+2], v[4*kg+3]);
            *reinterpret_cast<float4*>(&vals[t][4*kg]) = p;
        }
    }
    __syncthreads();

    // ---- Wait for zero_out_kernel completion (zeros visible in L2) ----
    cudaGridDependencySynchronize();

    // ---- Scatter: lane l -> edge (l/4), feature-group (l%4) ----
    // 4 consecutive lanes cover one contiguous 64B output row -> the warp's
    // RED.v4 merges into ~8 wavefronts instead of 32.
    const int kg = t & 3;
    const int eg = t >> 2;           // 0..63
#pragma unroll
    for (int q = 0; q < 4; q++) {
        const int el = eg + 64 * q;  // 0..255
        if (base + el < E) {
            const int s = sidx[el];                          // 4-lane broadcast
            float4 p = *reinterpret_cast<const float4*>(&vals[el][4*kg]);
            float* dst = out + (size_t)s * 16 + 4 * kg;      // 16B-aligned
            asm volatile("red.global.add.v4.f32 [%0], {%1, %2, %3, %4};"
                         :: "l"(dst), "f"(p.x), "f"(p.y), "f"(p.z), "f"(p.w)
                         : "memory");
        }
    }
}

// Generic fallback for F != 16 (plain serialized two-kernel path).
__global__ void zero_out_plain(float4* __restrict__ out, int n4) {
    for (int i = blockIdx.x * blockDim.x + threadIdx.x; i < n4;
         i += gridDim.x * blockDim.x)
        out[i] = make_float4(0.f, 0.f, 0.f, 0.f);
}
__global__ void scatter_generic_kernel(const float* __restrict__ attr,
                                       const int* __restrict__ src_idx,
                                       float* __restrict__ out,
                                       int E, int F) {
    int e = blockIdx.x * blockDim.x + threadIdx.x;
    if (e >= E) return;
    const int s = src_idx[e];
    for (int k = 0; k < F; k++)
        atomicAdd(&out[(size_t)s * F + k], attr[(size_t)k * E + e]);
}

extern "C" void kernel_launch(void* const* d_in, const int* in_sizes, int n_in,
                              void* d_out, int out_size) {
    const float* attr = (const float*)d_in[0];   // (E, F) float32, flat
    const int*   idx  = (const int*)d_in[1];     // (2, E) int32; row 0 = src

    const int E = in_sizes[1] / 2;
    const int F = in_sizes[0] / E;
    float* out = (float*)d_out;

    if (F == 16) {
        int n4 = out_size / 4;
        int zblocks = (n4 + 1023) / 1024;
        if (zblocks > 148) zblocks = 148;        // one wave, grid-stride
        zero_out_kernel<<<zblocks, 1024>>>((float4*)out, n4);

        int blocks = (E + TILE - 1) / TILE;
        cudaLaunchConfig_t cfg = {};
        cfg.gridDim = dim3((unsigned)blocks, 1, 1);
        cfg.blockDim = dim3(TILE, 1, 1);
        cfg.dynamicSmemBytes = 0;
        cfg.stream = 0;                          // same (captured) stream
        cudaLaunchAttribute attrs[1];
        attrs[0].id = cudaLaunchAttributeProgrammaticStreamSerialization;
        attrs[0].val.programmaticStreamSerializationAllowed = 1;
        cfg.attrs = attrs;
        cfg.numAttrs = 1;
        cudaLaunchKernelEx(&cfg, scatter_f16_kernel, attr, idx, out, E);
    } else {
        int n4 = out_size / 4;
        int zblocks = (n4 + 1023) / 1024;
        if (zblocks > 148) zblocks = 148;
        zero_out_plain<<<zblocks, 1024>>>((float4*)out, n4);
        int blocks = (E + 255) / 256;
        scatter_generic_kernel<<<blocks, 256>>>(attr, idx, out, E, F);
    }
}